// round 12
// baseline (speedup 1.0000x reference)
#include <cuda_runtime.h>
#include <cuda_fp16.h>

#define N_NODES 100000
#define N_EDGES 1600000
#define IN_F    128
#define OUT_F   64
#define NEG_SLOPE 0.2f
#define SCAN_ITEMS 1024
#define SCAN_BLOCKS ((N_NODES + SCAN_ITEMS - 1) / SCAN_ITEMS)   // 98
#define GEMM_TILE 64
#define GEMM_TILES ((N_NODES + GEMM_TILE - 1) / GEMM_TILE)      // 1563
#define APAD 136   // padded half-row stride (conflict-free ldmatrix)

// ---------------- device scratch (static, allocation-free) ----------------
__device__ __half   g_h[N_NODES * OUT_F];     // fp16 payload (unscaled h)
__device__ __half   g_x[N_NODES * OUT_F];
__device__ __half   g_y[N_NODES * OUT_F];
__device__ float2   g_sinfo[N_NODES];         // {el, outnorm}  (gemm.x / scan.y)
__device__ int2     g_dinfo[N_NODES];         // {er_bits, rowptr} (gemm.x / scan.y)
__device__ float    g_denom[N_NODES];
__device__ float    g_scfin[N_NODES];         // hop1 cache: innorm/denom
__device__ int      g_outdeg[N_NODES];
__device__ int      g_indeg[N_NODES];
__device__ float    g_innorm[N_NODES];
__device__ int      g_rowptr[N_NODES];
__device__ unsigned short g_rank[N_EDGES];    // edge's within-dst-row rank
__device__ int2     g_pack[N_EDGES];          // {src, (ee*outnorm_s)_bits}
// decoupled-lookback state: hi32 = flag (1=agg,2=prefix), lo32 = value
__device__ volatile unsigned long long g_state[SCAN_BLOCKS];

// second stream + fork/join events, created once at load time (no device mem)
namespace {
cudaStream_t g_s2;
cudaEvent_t  g_ev1, g_ev2;
struct InitStreams {
    InitStreams() {
        cudaStreamCreateWithFlags(&g_s2, cudaStreamNonBlocking);
        cudaEventCreateWithFlags(&g_ev1, cudaEventDisableTiming);
        cudaEventCreateWithFlags(&g_ev2, cudaEventDisableTiming);
    }
};
InitStreams g_init_streams;
}

__device__ __forceinline__ unsigned smemu(const void* p) {
    return (unsigned)__cvta_generic_to_shared(p);
}

// ---------------- K1: degrees + per-edge rank ----------------
__global__ void k_deg(const int* __restrict__ src, const int* __restrict__ dst) {
    int i = blockIdx.x * blockDim.x + threadIdx.x;
    if (i >= N_EDGES) return;
    atomicAdd(&g_outdeg[__ldg(src + i)], 1);
    g_rank[i] = (unsigned short)atomicAdd(&g_indeg[__ldg(dst + i)], 1);
}

// ---------------- K2: single-pass scan, warp-parallel lookback + norms ----
__global__ void __launch_bounds__(256) k_scan() {
    __shared__ int sh[256];
    __shared__ int s_prefix;
    int t = threadIdx.x, b = blockIdx.x;
    int base = b * SCAN_ITEMS + t * 4;
    int v0 = 0, v1 = 0, v2 = 0, v3 = 0;
    if (base + 0 < N_NODES) v0 = g_indeg[base + 0];
    if (base + 1 < N_NODES) v1 = g_indeg[base + 1];
    if (base + 2 < N_NODES) v2 = g_indeg[base + 2];
    if (base + 3 < N_NODES) v3 = g_indeg[base + 3];
    int s = v0 + v1 + v2 + v3;
    sh[t] = s;
    __syncthreads();
    for (int o = 1; o < 256; o <<= 1) {
        int x = (t >= o) ? sh[t - o] : 0;
        __syncthreads();
        sh[t] += x;
        __syncthreads();
    }
    int total = sh[255];
    if (t == 0) {
        if (b == 0) g_state[0] = (2ull << 32) | (unsigned)total;
        else        g_state[b] = (1ull << 32) | (unsigned)total;
    }
    if (t < 32) {
        int pfx = 0;
        if (b > 0) {
            int base_j = b - 1;
            for (;;) {
                int j = base_j - t;
                int flag, val;
                if (j >= 0) {
                    unsigned long long st;
                    do { st = g_state[j]; } while ((st >> 32) == 0);
                    flag = (int)(st >> 32); val = (int)(unsigned)st;
                } else { flag = 2; val = 0; }
                unsigned m2 = __ballot_sync(0xffffffffu, flag == 2);
                int first = __ffs(m2) - 1;
                int contrib = (m2 == 0) ? val : ((t <= first) ? val : 0);
#pragma unroll
                for (int o = 16; o; o >>= 1)
                    contrib += __shfl_xor_sync(0xffffffffu, contrib, o);
                pfx += contrib;
                if (m2) break;
                base_j -= 32;
            }
            if (t == 0) g_state[b] = (2ull << 32) | (unsigned)(pfx + total);
        }
        if (t == 0) s_prefix = pfx;
    }
    __syncthreads();
    int excl = s_prefix + sh[t] - s;
    int e0 = excl, e1 = excl + v0, e2 = e1 + v1, e3 = e2 + v2;
#pragma unroll
    for (int j = 0; j < 4; j++) {
        int n = base + j;
        if (n >= N_NODES) break;
        int r = (j == 0) ? e0 : (j == 1) ? e1 : (j == 2) ? e2 : e3;
        g_rowptr[n] = r;
        g_dinfo[n].y = r;
        int od = g_outdeg[n]; if (od < 1) od = 1;
        int id = (j == 0) ? v0 : (j == 1) ? v1 : (j == 2) ? v2 : v3;
        if (id < 1) id = 1;
        g_sinfo[n].y = rsqrtf((float)od);     // outnorm
        g_innorm[n]  = sqrtf((float)id);
    }
}

// ---------------- K0: h = feat @ W^T via HMMA (unscaled payload) ----------
__global__ void __launch_bounds__(128) k_gemm(const float* __restrict__ feat,
                                              const float* __restrict__ W,
                                              const float* __restrict__ attn_l,
                                              const float* __restrict__ attn_r) {
    __shared__ __half sA[GEMM_TILE * APAD];
    __shared__ __half sB[OUT_F * APAD];
    int t = threadIdx.x;
    int warp = t >> 5, lane = t & 31;
    int node0 = blockIdx.x * GEMM_TILE;

#pragma unroll
    for (int i = 0; i < 16; i++) {
        int lin = t * 4 + i * 512;
        int o = lin >> 7, k = lin & 127;
        float4 w4 = __ldg((const float4*)(W + lin));
        *(__half2*)(sB + o * APAD + k)     = __floats2half2_rn(w4.x, w4.y);
        *(__half2*)(sB + o * APAD + k + 2) = __floats2half2_rn(w4.z, w4.w);
    }
#pragma unroll
    for (int i = 0; i < 16; i++) {
        int lin = t * 4 + i * 512;
        int r = lin >> 7, k = lin & 127;
        int node = node0 + r; if (node > N_NODES - 1) node = N_NODES - 1;
        float4 f4 = __ldg((const float4*)(feat + (size_t)node * IN_F + k));
        *(__half2*)(sA + r * APAD + k)     = __floats2half2_rn(f4.x, f4.y);
        *(__half2*)(sA + r * APAD + k + 2) = __floats2half2_rn(f4.z, f4.w);
    }
    __syncthreads();

    int m0 = warp * 16;
    int lr  = lane & 7;
    int grp = lane >> 3;
    int a_m = m0 + lr + ((grp & 1) ? 8 : 0);
    int a_k = (grp & 2) ? 8 : 0;
    unsigned aBase = smemu(sA) + (unsigned)(a_m * APAD + a_k) * 2;
    int b_n = lane & 7;
    int b_k = ((lane >> 3) & 1) ? 8 : 0;
    unsigned bBase = smemu(sB) + (unsigned)(b_n * APAD + b_k) * 2;

    float c[8][4];
#pragma unroll
    for (int nt = 0; nt < 8; nt++) { c[nt][0] = c[nt][1] = c[nt][2] = c[nt][3] = 0.f; }

#pragma unroll
    for (int ks = 0; ks < 8; ks++) {
        unsigned a0, a1, a2, a3;
        asm volatile("ldmatrix.sync.aligned.m8n8.x4.shared.b16 {%0,%1,%2,%3}, [%4];"
                     : "=r"(a0), "=r"(a1), "=r"(a2), "=r"(a3)
                     : "r"(aBase + ks * 32));
#pragma unroll
        for (int nt = 0; nt < 8; nt++) {
            unsigned b0, b1;
            asm volatile("ldmatrix.sync.aligned.m8n8.x2.shared.b16 {%0,%1}, [%2];"
                         : "=r"(b0), "=r"(b1)
                         : "r"(bBase + nt * (8 * APAD * 2) + ks * 32));
            asm volatile("mma.sync.aligned.m16n8k16.row.col.f32.f16.f16.f32 "
                         "{%0,%1,%2,%3}, {%4,%5,%6,%7}, {%8,%9}, {%0,%1,%2,%3};"
                         : "+f"(c[nt][0]), "+f"(c[nt][1]), "+f"(c[nt][2]), "+f"(c[nt][3])
                         : "r"(a0), "r"(a1), "r"(a2), "r"(a3), "r"(b0), "r"(b1));
        }
    }

    int q  = lane & 3;
    int mr = lane >> 2;
    int nodeA = node0 + m0 + mr;
    int nodeB = nodeA + 8;
    bool va = nodeA < N_NODES, vb = nodeB < N_NODES;
    float el0 = 0.f, er0 = 0.f, el1 = 0.f, er1 = 0.f;
    __half2* h2 = (__half2*)g_h;
#pragma unroll
    for (int nt = 0; nt < 8; nt++) {
        float2 alv = __ldg((const float2*)attn_l + nt * 4 + q);
        float2 arv = __ldg((const float2*)attn_r + nt * 4 + q);
        el0 += c[nt][0] * alv.x + c[nt][1] * alv.y;
        er0 += c[nt][0] * arv.x + c[nt][1] * arv.y;
        el1 += c[nt][2] * alv.x + c[nt][3] * alv.y;
        er1 += c[nt][2] * arv.x + c[nt][3] * arv.y;
        if (va) h2[(size_t)nodeA * 32 + nt * 4 + q] = __floats2half2_rn(c[nt][0], c[nt][1]);
        if (vb) h2[(size_t)nodeB * 32 + nt * 4 + q] = __floats2half2_rn(c[nt][2], c[nt][3]);
    }
#pragma unroll
    for (int o = 1; o <= 2; o <<= 1) {
        el0 += __shfl_xor_sync(0xffffffffu, el0, o);
        er0 += __shfl_xor_sync(0xffffffffu, er0, o);
        el1 += __shfl_xor_sync(0xffffffffu, el1, o);
        er1 += __shfl_xor_sync(0xffffffffu, er1, o);
    }
    if (q == 0) {
        if (va) { g_sinfo[nodeA].x = el0; g_dinfo[nodeA].x = __float_as_int(er0); }
        if (vb) { g_sinfo[nodeB].x = el1; g_dinfo[nodeB].x = __float_as_int(er1); }
    }
}

// ---------------- K3: edge pass: ee, denom, CSR fill ----------------------
__global__ void k_edge2(const int* __restrict__ src, const int* __restrict__ dst) {
    int i = blockIdx.x * blockDim.x + threadIdx.x;
    if (i >= N_EDGES) return;
    int s = __ldg(src + i), d = __ldg(dst + i);
    float2 si = __ldg(&g_sinfo[s]);               // {el, outnorm}
    int2   di = __ldg(&g_dinfo[d]);               // {er_bits, rowptr}
    float e = si.x + __int_as_float(di.x);
    e = e > 0.f ? e : NEG_SLOPE * e;
    float ee = __expf(e);
    atomicAdd(&g_denom[d], ee);
    int pos = di.y + (int)__ldg(&g_rank[i]);
    g_pack[pos] = make_int2(s, __float_as_int(ee * si.y));
}

// ---------------- K4: hop — 8 lanes/node, uint4 fp16 gathers --------------
__device__ __forceinline__ void fma8(float4& a0, float4& a1, float c, uint4 u) {
    float2 f;
    f = __half22float2(*(__half2*)&u.x); a0.x += c * f.x; a0.y += c * f.y;
    f = __half22float2(*(__half2*)&u.y); a0.z += c * f.x; a0.w += c * f.y;
    f = __half22float2(*(__half2*)&u.z); a1.x += c * f.x; a1.y += c * f.y;
    f = __half22float2(*(__half2*)&u.w); a1.z += c * f.x; a1.w += c * f.y;
}

// MODE 0: first hop  — compute scfin = innorm/denom, cache; fp16 out
// MODE 1: middle hop — cached scfin; fp16 out
// MODE 2: final hop  — cached scfin; fp32 out
template <int MODE>
__global__ void __launch_bounds__(256) k_hop(const __half* __restrict__ cur,
                                             void* __restrict__ nxt) {
    unsigned g = blockIdx.x * blockDim.x + threadIdx.x;
    unsigned n = g >> 3;
    if (n >= N_NODES) return;
    int lane = g & 7;
    int beg = g_rowptr[n];
    int end = beg + g_indeg[n];
    const uint4* cur4 = (const uint4*)cur;   // 8 uint4 per row
    float4 a0 = make_float4(0.f, 0.f, 0.f, 0.f);
    float4 a1 = make_float4(0.f, 0.f, 0.f, 0.f);
    int p = beg;
    for (; p + 3 < end; p += 4) {
        int2 k0 = __ldg(&g_pack[p]);
        int2 k1 = __ldg(&g_pack[p + 1]);
        int2 k2 = __ldg(&g_pack[p + 2]);
        int2 k3 = __ldg(&g_pack[p + 3]);
        uint4 u0 = __ldg(&cur4[(size_t)k0.x * 8 + lane]);
        uint4 u1 = __ldg(&cur4[(size_t)k1.x * 8 + lane]);
        uint4 u2 = __ldg(&cur4[(size_t)k2.x * 8 + lane]);
        uint4 u3 = __ldg(&cur4[(size_t)k3.x * 8 + lane]);
        fma8(a0, a1, __int_as_float(k0.y), u0);
        fma8(a0, a1, __int_as_float(k1.y), u1);
        fma8(a0, a1, __int_as_float(k2.y), u2);
        fma8(a0, a1, __int_as_float(k3.y), u3);
    }
    for (; p < end; p++) {
        int2 k0 = __ldg(&g_pack[p]);
        uint4 u0 = __ldg(&cur4[(size_t)k0.x * 8 + lane]);
        fma8(a0, a1, __int_as_float(k0.y), u0);
    }
    float sc;
    if (MODE == 0) {
        float dn = g_denom[n];
        sc = dn > 0.f ? g_innorm[n] / dn : 0.f;
        if (lane == 0) g_scfin[n] = sc;
    } else {
        sc = g_scfin[n];
    }
    a0.x *= sc; a0.y *= sc; a0.z *= sc; a0.w *= sc;
    a1.x *= sc; a1.y *= sc; a1.z *= sc; a1.w *= sc;
    if (MODE == 2) {
        ((float4*)nxt)[(size_t)n * 16 + lane * 2]     = a0;
        ((float4*)nxt)[(size_t)n * 16 + lane * 2 + 1] = a1;
    } else {
        __half2 h0 = __floats2half2_rn(a0.x, a0.y);
        __half2 h1 = __floats2half2_rn(a0.z, a0.w);
        __half2 h2 = __floats2half2_rn(a1.x, a1.y);
        __half2 h3 = __floats2half2_rn(a1.z, a1.w);
        uint4 u;
        u.x = *(unsigned*)&h0; u.y = *(unsigned*)&h1;
        u.z = *(unsigned*)&h2; u.w = *(unsigned*)&h3;
        ((uint4*)nxt)[(size_t)n * 8 + lane] = u;
    }
}

// ---------------- launch ----------------
extern "C" void kernel_launch(void* const* d_in, const int* in_sizes, int n_in,
                              void* d_out, int out_size) {
    const float* feat   = (const float*)d_in[0];
    const float* W      = (const float*)d_in[1];
    const float* attn_l = (const float*)d_in[2];
    const float* attn_r = (const float*)d_in[3];
    const int*   src    = (const int*)d_in[4];
    const int*   dst    = (const int*)d_in[5];
    float*       out    = (float*)d_out;

    void *p_denom, *p_od, *p_id, *p_x, *p_y, *p_h, *p_state;
    cudaGetSymbolAddress(&p_denom, g_denom);
    cudaGetSymbolAddress(&p_od,    g_outdeg);
    cudaGetSymbolAddress(&p_id,    g_indeg);
    cudaGetSymbolAddress(&p_x,     g_x);
    cudaGetSymbolAddress(&p_y,     g_y);
    cudaGetSymbolAddress(&p_h,     g_h);
    cudaGetSymbolAddress(&p_state, (const void*)g_state);

    // fork: GEMM (independent of degree/scan chain) runs on g_s2
    cudaEventRecord(g_ev1, 0);
    cudaStreamWaitEvent(g_s2, g_ev1, 0);
    k_gemm<<<GEMM_TILES, 128, 0, g_s2>>>(feat, W, attn_l, attn_r);
    cudaEventRecord(g_ev2, g_s2);

    // main stream: memsets + degree + scan
    cudaMemsetAsync(p_denom, 0, N_NODES * sizeof(float));
    cudaMemsetAsync(p_od,    0, N_NODES * sizeof(int));
    cudaMemsetAsync(p_id,    0, N_NODES * sizeof(int));
    cudaMemsetAsync(p_state, 0, SCAN_BLOCKS * sizeof(unsigned long long));
    k_deg<<<(N_EDGES + 255) / 256, 256>>>(src, dst);
    k_scan<<<SCAN_BLOCKS, 256>>>();

    // join: edge2 needs both branches
    cudaStreamWaitEvent(0, g_ev2, 0);
    k_edge2<<<(N_EDGES + 255) / 256, 256>>>(src, dst);

    const int hop_blocks = (N_NODES * 8 + 255) / 256;  // 3125
    k_hop<0><<<hop_blocks, 256>>>((const __half*)p_h, p_x);
    k_hop<1><<<hop_blocks, 256>>>((const __half*)p_x, p_y);
    k_hop<2><<<hop_blocks, 256>>>((const __half*)p_y, out);
}

// round 14
// speedup vs baseline: 1.0810x; 1.0810x over previous
#include <cuda_runtime.h>
#include <cuda_fp16.h>

#define N_NODES 100000
#define N_EDGES 1600000
#define IN_F    128
#define OUT_F   64
#define NEG_SLOPE 0.2f
#define SCAN_ITEMS 1024
#define SCAN_BLOCKS ((N_NODES + SCAN_ITEMS - 1) / SCAN_ITEMS)   // 98
#define GEMM_TILE 64
#define GEMM_TILES ((N_NODES + GEMM_TILE - 1) / GEMM_TILE)      // 1563
#define APAD 136   // padded half-row stride (conflict-free ldmatrix)

// ---------------- device scratch (static, allocation-free) ----------------
__device__ __half   g_h[N_NODES * OUT_F];     // fp16 payload: h * outnorm
__device__ __half   g_x[N_NODES * OUT_F];
__device__ __half   g_y[N_NODES * OUT_F];
__device__ float    g_el[N_NODES];
__device__ int2     g_dinfo[N_NODES];         // {er_bits, rowptr} for edge2
__device__ int2     g_ninfo[N_NODES];         // {rowptr, indeg} for hops
__device__ float    g_scfin[N_NODES];         // hop1 cache: innorm/denom
__device__ float    g_outnorm[N_NODES];
__device__ float    g_innorm[N_NODES];        // after hop1: scmid
__device__ unsigned short g_rank[N_EDGES];    // edge's within-dst-row rank
__device__ int2     g_pack[N_EDGES];          // {src, ee_bits}

// single zero-init region: [outdeg | indeg | lookback state]
__device__ int      g_zbuf[2 * N_NODES + 2 * SCAN_BLOCKS];
#define G_OUTDEG (g_zbuf)
#define G_INDEG  (g_zbuf + N_NODES)
#define G_STATE  ((volatile unsigned long long*)(g_zbuf + 2 * N_NODES))
#define ZBUF_BYTES ((2 * N_NODES + 2 * SCAN_BLOCKS) * sizeof(int))

__device__ __forceinline__ unsigned smemu(const void* p) {
    return (unsigned)__cvta_generic_to_shared(p);
}

// ---------------- K1: degrees + per-edge rank (4 edges/thread) ------------
__global__ void k_deg(const int4* __restrict__ src4, const int4* __restrict__ dst4) {
    int i = blockIdx.x * blockDim.x + threadIdx.x;
    if (i >= N_EDGES / 4) return;
    int4 s = __ldg(src4 + i);
    int4 d = __ldg(dst4 + i);
    atomicAdd(&G_OUTDEG[s.x], 1);
    atomicAdd(&G_OUTDEG[s.y], 1);
    atomicAdd(&G_OUTDEG[s.z], 1);
    atomicAdd(&G_OUTDEG[s.w], 1);
    ushort4 r;
    r.x = (unsigned short)atomicAdd(&G_INDEG[d.x], 1);
    r.y = (unsigned short)atomicAdd(&G_INDEG[d.y], 1);
    r.z = (unsigned short)atomicAdd(&G_INDEG[d.z], 1);
    r.w = (unsigned short)atomicAdd(&G_INDEG[d.w], 1);
    *(ushort4*)(g_rank + i * 4) = r;
}

// ---------------- K2: single-pass scan, warp-parallel lookback + norms ----
__global__ void __launch_bounds__(256) k_scan() {
    __shared__ int sh[256];
    __shared__ int s_prefix;
    int t = threadIdx.x, b = blockIdx.x;
    int base = b * SCAN_ITEMS + t * 4;
    int v0 = 0, v1 = 0, v2 = 0, v3 = 0;
    if (base + 0 < N_NODES) v0 = G_INDEG[base + 0];
    if (base + 1 < N_NODES) v1 = G_INDEG[base + 1];
    if (base + 2 < N_NODES) v2 = G_INDEG[base + 2];
    if (base + 3 < N_NODES) v3 = G_INDEG[base + 3];
    int s = v0 + v1 + v2 + v3;
    sh[t] = s;
    __syncthreads();
    for (int o = 1; o < 256; o <<= 1) {
        int x = (t >= o) ? sh[t - o] : 0;
        __syncthreads();
        sh[t] += x;
        __syncthreads();
    }
    int total = sh[255];
    if (t == 0) {
        if (b == 0) G_STATE[0] = (2ull << 32) | (unsigned)total;
        else        G_STATE[b] = (1ull << 32) | (unsigned)total;
    }
    if (t < 32) {
        int pfx = 0;
        if (b > 0) {
            int base_j = b - 1;
            for (;;) {
                int j = base_j - t;
                int flag, val;
                if (j >= 0) {
                    unsigned long long st;
                    do { st = G_STATE[j]; } while ((st >> 32) == 0);
                    flag = (int)(st >> 32); val = (int)(unsigned)st;
                } else { flag = 2; val = 0; }
                unsigned m2 = __ballot_sync(0xffffffffu, flag == 2);
                int first = __ffs(m2) - 1;
                int contrib = (m2 == 0) ? val : ((t <= first) ? val : 0);
#pragma unroll
                for (int o = 16; o; o >>= 1)
                    contrib += __shfl_xor_sync(0xffffffffu, contrib, o);
                pfx += contrib;
                if (m2) break;
                base_j -= 32;
            }
            if (t == 0) G_STATE[b] = (2ull << 32) | (unsigned)(pfx + total);
        }
        if (t == 0) s_prefix = pfx;
    }
    __syncthreads();
    int excl = s_prefix + sh[t] - s;
    int e0 = excl, e1 = excl + v0, e2 = e1 + v1, e3 = e2 + v2;
#pragma unroll
    for (int j = 0; j < 4; j++) {
        int n = base + j;
        if (n >= N_NODES) break;
        int r  = (j == 0) ? e0 : (j == 1) ? e1 : (j == 2) ? e2 : e3;
        int id = (j == 0) ? v0 : (j == 1) ? v1 : (j == 2) ? v2 : v3;
        g_dinfo[n].y = r;
        g_ninfo[n] = make_int2(r, id);
        int od = G_OUTDEG[n]; if (od < 1) od = 1;
        int idc = id < 1 ? 1 : id;
        g_outnorm[n] = rsqrtf((float)od);
        g_innorm[n]  = sqrtf((float)idc);
    }
}

// ---------------- K0: h = feat @ W^T via HMMA, payload *= outnorm ---------
__global__ void __launch_bounds__(128) k_gemm(const float* __restrict__ feat,
                                              const float* __restrict__ W,
                                              const float* __restrict__ attn_l,
                                              const float* __restrict__ attn_r) {
    __shared__ __half sA[GEMM_TILE * APAD];
    __shared__ __half sB[OUT_F * APAD];
    int t = threadIdx.x;
    int warp = t >> 5, lane = t & 31;
    int node0 = blockIdx.x * GEMM_TILE;

#pragma unroll
    for (int i = 0; i < 16; i++) {
        int lin = t * 4 + i * 512;
        int o = lin >> 7, k = lin & 127;
        float4 w4 = __ldg((const float4*)(W + lin));
        *(__half2*)(sB + o * APAD + k)     = __floats2half2_rn(w4.x, w4.y);
        *(__half2*)(sB + o * APAD + k + 2) = __floats2half2_rn(w4.z, w4.w);
    }
#pragma unroll
    for (int i = 0; i < 16; i++) {
        int lin = t * 4 + i * 512;
        int r = lin >> 7, k = lin & 127;
        int node = node0 + r; if (node > N_NODES - 1) node = N_NODES - 1;
        float4 f4 = __ldg((const float4*)(feat + (size_t)node * IN_F + k));
        *(__half2*)(sA + r * APAD + k)     = __floats2half2_rn(f4.x, f4.y);
        *(__half2*)(sA + r * APAD + k + 2) = __floats2half2_rn(f4.z, f4.w);
    }
    __syncthreads();

    int m0 = warp * 16;
    int lr  = lane & 7;
    int grp = lane >> 3;
    int a_m = m0 + lr + ((grp & 1) ? 8 : 0);
    int a_k = (grp & 2) ? 8 : 0;
    unsigned aBase = smemu(sA) + (unsigned)(a_m * APAD + a_k) * 2;
    int b_n = lane & 7;
    int b_k = ((lane >> 3) & 1) ? 8 : 0;
    unsigned bBase = smemu(sB) + (unsigned)(b_n * APAD + b_k) * 2;

    float c[8][4];
#pragma unroll
    for (int nt = 0; nt < 8; nt++) { c[nt][0] = c[nt][1] = c[nt][2] = c[nt][3] = 0.f; }

#pragma unroll
    for (int ks = 0; ks < 8; ks++) {
        unsigned a0, a1, a2, a3;
        asm volatile("ldmatrix.sync.aligned.m8n8.x4.shared.b16 {%0,%1,%2,%3}, [%4];"
                     : "=r"(a0), "=r"(a1), "=r"(a2), "=r"(a3)
                     : "r"(aBase + ks * 32));
#pragma unroll
        for (int nt = 0; nt < 8; nt++) {
            unsigned b0, b1;
            asm volatile("ldmatrix.sync.aligned.m8n8.x2.shared.b16 {%0,%1}, [%2];"
                         : "=r"(b0), "=r"(b1)
                         : "r"(bBase + nt * (8 * APAD * 2) + ks * 32));
            asm volatile("mma.sync.aligned.m16n8k16.row.col.f32.f16.f16.f32 "
                         "{%0,%1,%2,%3}, {%4,%5,%6,%7}, {%8,%9}, {%0,%1,%2,%3};"
                         : "+f"(c[nt][0]), "+f"(c[nt][1]), "+f"(c[nt][2]), "+f"(c[nt][3])
                         : "r"(a0), "r"(a1), "r"(a2), "r"(a3), "r"(b0), "r"(b1));
        }
    }

    int q  = lane & 3;
    int mr = lane >> 2;
    int nodeA = node0 + m0 + mr;
    int nodeB = nodeA + 8;
    bool va = nodeA < N_NODES, vb = nodeB < N_NODES;
    float onA = va ? g_outnorm[nodeA] : 0.f;
    float onB = vb ? g_outnorm[nodeB] : 0.f;
    float el0 = 0.f, er0 = 0.f, el1 = 0.f, er1 = 0.f;
    __half2* h2 = (__half2*)g_h;
#pragma unroll
    for (int nt = 0; nt < 8; nt++) {
        float2 alv = __ldg((const float2*)attn_l + nt * 4 + q);
        float2 arv = __ldg((const float2*)attn_r + nt * 4 + q);
        el0 += c[nt][0] * alv.x + c[nt][1] * alv.y;
        er0 += c[nt][0] * arv.x + c[nt][1] * arv.y;
        el1 += c[nt][2] * alv.x + c[nt][3] * alv.y;
        er1 += c[nt][2] * arv.x + c[nt][3] * arv.y;
        if (va) h2[(size_t)nodeA * 32 + nt * 4 + q] =
            __floats2half2_rn(c[nt][0] * onA, c[nt][1] * onA);
        if (vb) h2[(size_t)nodeB * 32 + nt * 4 + q] =
            __floats2half2_rn(c[nt][2] * onB, c[nt][3] * onB);
    }
#pragma unroll
    for (int o = 1; o <= 2; o <<= 1) {
        el0 += __shfl_xor_sync(0xffffffffu, el0, o);
        er0 += __shfl_xor_sync(0xffffffffu, er0, o);
        el1 += __shfl_xor_sync(0xffffffffu, el1, o);
        er1 += __shfl_xor_sync(0xffffffffu, er1, o);
    }
    if (q == 0) {
        if (va) { g_el[nodeA] = el0; g_dinfo[nodeA].x = __float_as_int(er0); }
        if (vb) { g_el[nodeB] = el1; g_dinfo[nodeB].x = __float_as_int(er1); }
    }
}

// ---------------- K3: edge pass: ee, CSR fill (no atomics) ----------------
__global__ void k_edge2(const int* __restrict__ src, const int* __restrict__ dst) {
    int i = blockIdx.x * blockDim.x + threadIdx.x;
    if (i >= N_EDGES) return;
    int s = __ldg(src + i), d = __ldg(dst + i);
    int2 di = __ldg(&g_dinfo[d]);                 // {er_bits, rowptr}
    float e = __ldg(&g_el[s]) + __int_as_float(di.x);
    e = e > 0.f ? e : NEG_SLOPE * e;
    float ee = __expf(e);
    int pos = di.y + (int)__ldg(&g_rank[i]);
    g_pack[pos] = make_int2(s, __float_as_int(ee));
}

// ---------------- K4: hop — 8 lanes/node, uint4 fp16 gathers --------------
__device__ __forceinline__ void fma8(float4& a0, float4& a1, float c, uint4 u) {
    float2 f;
    f = __half22float2(*(__half2*)&u.x); a0.x += c * f.x; a0.y += c * f.y;
    f = __half22float2(*(__half2*)&u.y); a0.z += c * f.x; a0.w += c * f.y;
    f = __half22float2(*(__half2*)&u.z); a1.x += c * f.x; a1.y += c * f.y;
    f = __half22float2(*(__half2*)&u.w); a1.z += c * f.x; a1.w += c * f.y;
}

// MODE 0: first hop  — denom = local sum of coefs; compute+cache scales
// MODE 1: middle hop — scale by cached scmid, write fp16 payload
// MODE 2: final hop  — scale by cached scfin, write fp32 output
template <int MODE>
__global__ void __launch_bounds__(256) k_hop(const __half* __restrict__ cur,
                                             void* __restrict__ nxt) {
    unsigned g = blockIdx.x * blockDim.x + threadIdx.x;
    unsigned n = g >> 3;
    if (n >= N_NODES) return;
    int lane = g & 7;
    int2 ni = __ldg(&g_ninfo[n]);            // {rowptr, indeg}
    int beg = ni.x;
    int end = beg + ni.y;
    const uint4* cur4 = (const uint4*)cur;   // 8 uint4 per row
    float4 a0 = make_float4(0.f, 0.f, 0.f, 0.f);
    float4 a1 = make_float4(0.f, 0.f, 0.f, 0.f);
    float dsum = 0.f;
    int p = beg;
    for (; p + 3 < end; p += 4) {
        int2 k0 = __ldg(&g_pack[p]);
        int2 k1 = __ldg(&g_pack[p + 1]);
        int2 k2 = __ldg(&g_pack[p + 2]);
        int2 k3 = __ldg(&g_pack[p + 3]);
        uint4 u0 = __ldg(&cur4[(size_t)k0.x * 8 + lane]);
        uint4 u1 = __ldg(&cur4[(size_t)k1.x * 8 + lane]);
        uint4 u2 = __ldg(&cur4[(size_t)k2.x * 8 + lane]);
        uint4 u3 = __ldg(&cur4[(size_t)k3.x * 8 + lane]);
        float c0 = __int_as_float(k0.y), c1 = __int_as_float(k1.y);
        float c2 = __int_as_float(k2.y), c3 = __int_as_float(k3.y);
        if (MODE == 0) dsum += (c0 + c1) + (c2 + c3);
        fma8(a0, a1, c0, u0); fma8(a0, a1, c1, u1);
        fma8(a0, a1, c2, u2); fma8(a0, a1, c3, u3);
    }
    for (; p < end; p++) {
        int2 k0 = __ldg(&g_pack[p]);
        uint4 u0 = __ldg(&cur4[(size_t)k0.x * 8 + lane]);
        float c0 = __int_as_float(k0.y);
        if (MODE == 0) dsum += c0;
        fma8(a0, a1, c0, u0);
    }
    float sc;
    if (MODE == 0) {
        float scfin = dsum > 0.f ? g_innorm[n] / dsum : 0.f;
        float scmid = scfin * g_outnorm[n];
        if (lane == 0) { g_innorm[n] = scmid; g_scfin[n] = scfin; }
        sc = scmid;
    } else if (MODE == 1) {
        sc = g_innorm[n];
    } else {
        sc = g_scfin[n];
    }
    a0.x *= sc; a0.y *= sc; a0.z *= sc; a0.w *= sc;
    a1.x *= sc; a1.y *= sc; a1.z *= sc; a1.w *= sc;
    if (MODE == 2) {
        ((float4*)nxt)[(size_t)n * 16 + lane * 2]     = a0;
        ((float4*)nxt)[(size_t)n * 16 + lane * 2 + 1] = a1;
    } else {
        __half2 h0 = __floats2half2_rn(a0.x, a0.y);
        __half2 h1 = __floats2half2_rn(a0.z, a0.w);
        __half2 h2 = __floats2half2_rn(a1.x, a1.y);
        __half2 h3 = __floats2half2_rn(a1.z, a1.w);
        uint4 u;
        u.x = *(unsigned*)&h0; u.y = *(unsigned*)&h1;
        u.z = *(unsigned*)&h2; u.w = *(unsigned*)&h3;
        ((uint4*)nxt)[(size_t)n * 8 + lane] = u;
    }
}

// ---------------- launch ----------------
extern "C" void kernel_launch(void* const* d_in, const int* in_sizes, int n_in,
                              void* d_out, int out_size) {
    const float* feat   = (const float*)d_in[0];
    const float* W      = (const float*)d_in[1];
    const float* attn_l = (const float*)d_in[2];
    const float* attn_r = (const float*)d_in[3];
    const int*   src    = (const int*)d_in[4];
    const int*   dst    = (const int*)d_in[5];
    float*       out    = (float*)d_out;

    void *p_zbuf, *p_x, *p_y, *p_h;
    cudaGetSymbolAddress(&p_zbuf, g_zbuf);
    cudaGetSymbolAddress(&p_x,    g_x);
    cudaGetSymbolAddress(&p_y,    g_y);
    cudaGetSymbolAddress(&p_h,    g_h);

    cudaMemsetAsync(p_zbuf, 0, ZBUF_BYTES);

    k_deg<<<(N_EDGES / 4 + 255) / 256, 256>>>((const int4*)src, (const int4*)dst);
    k_scan<<<SCAN_BLOCKS, 256>>>();
    k_gemm<<<GEMM_TILES, 128>>>(feat, W, attn_l, attn_r);
    k_edge2<<<(N_EDGES + 255) / 256, 256>>>(src, dst);

    const int hop_blocks = (N_NODES * 8 + 255) / 256;  // 3125
    k_hop<0><<<hop_blocks, 256>>>((const __half*)p_h, p_x);
    k_hop<1><<<hop_blocks, 256>>>((const __half*)p_x, p_y);
    k_hop<2><<<hop_blocks, 256>>>((const __half*)p_y, out);
}

// round 15
// speedup vs baseline: 1.0951x; 1.0131x over previous
#include <cuda_runtime.h>
#include <cuda_fp16.h>

#define N_NODES 100000
#define N_EDGES 1600000
#define IN_F    128
#define OUT_F   64
#define NEG_SLOPE 0.2f
#define SCAN_ITEMS 1024
#define SCAN_BLOCKS ((N_NODES + SCAN_ITEMS - 1) / SCAN_ITEMS)   // 98
#define GEMM_TILE 64
#define GEMM_TILES ((N_NODES + GEMM_TILE - 1) / GEMM_TILE)      // 1563
#define GEMM_GRID 592
#define APAD 136   // padded half-row stride (conflict-free ldmatrix)

// ---------------- device scratch (static, allocation-free) ----------------
__device__ __half   g_h[N_NODES * OUT_F];     // fp16 payload: h * outnorm
__device__ __half   g_x[N_NODES * OUT_F];
__device__ __half   g_y[N_NODES * OUT_F];
__device__ float    g_el[N_NODES];
__device__ int2     g_dinfo[N_NODES];         // {er_bits, rowptr} for edge2
__device__ int2     g_ninfo[N_NODES];         // {rowptr, indeg} for hops
__device__ float    g_scfin[N_NODES];         // hop1 cache: innorm/denom
__device__ float    g_outnorm[N_NODES];
__device__ float    g_innorm[N_NODES];        // after hop1: scmid
__device__ unsigned short g_rank[N_EDGES];    // edge's within-dst-row rank
__device__ int2     g_pack[N_EDGES];          // {src, ee_bits}

// single zero-init region: [outdeg | indeg | lookback state]
__device__ int      g_zbuf[2 * N_NODES + 2 * SCAN_BLOCKS];
#define G_OUTDEG (g_zbuf)
#define G_INDEG  (g_zbuf + N_NODES)
#define G_STATE  ((volatile unsigned long long*)(g_zbuf + 2 * N_NODES))
#define ZBUF_BYTES ((2 * N_NODES + 2 * SCAN_BLOCKS) * sizeof(int))

__device__ __forceinline__ unsigned smemu(const void* p) {
    return (unsigned)__cvta_generic_to_shared(p);
}

// ---------------- K1: degrees + per-edge rank (4 edges/thread) ------------
__global__ void k_deg(const int4* __restrict__ src4, const int4* __restrict__ dst4) {
    int i = blockIdx.x * blockDim.x + threadIdx.x;
    if (i >= N_EDGES / 4) return;
    int4 s = __ldg(src4 + i);
    int4 d = __ldg(dst4 + i);
    atomicAdd(&G_OUTDEG[s.x], 1);
    atomicAdd(&G_OUTDEG[s.y], 1);
    atomicAdd(&G_OUTDEG[s.z], 1);
    atomicAdd(&G_OUTDEG[s.w], 1);
    ushort4 r;
    r.x = (unsigned short)atomicAdd(&G_INDEG[d.x], 1);
    r.y = (unsigned short)atomicAdd(&G_INDEG[d.y], 1);
    r.z = (unsigned short)atomicAdd(&G_INDEG[d.z], 1);
    r.w = (unsigned short)atomicAdd(&G_INDEG[d.w], 1);
    *(ushort4*)(g_rank + i * 4) = r;
}

// ---------------- K2: single-pass scan, warp-parallel lookback + norms ----
__global__ void __launch_bounds__(256) k_scan() {
    __shared__ int sh[256];
    __shared__ int s_prefix;
    int t = threadIdx.x, b = blockIdx.x;
    int base = b * SCAN_ITEMS + t * 4;
    int v0 = 0, v1 = 0, v2 = 0, v3 = 0;
    if (base + 0 < N_NODES) v0 = G_INDEG[base + 0];
    if (base + 1 < N_NODES) v1 = G_INDEG[base + 1];
    if (base + 2 < N_NODES) v2 = G_INDEG[base + 2];
    if (base + 3 < N_NODES) v3 = G_INDEG[base + 3];
    int s = v0 + v1 + v2 + v3;
    sh[t] = s;
    __syncthreads();
    for (int o = 1; o < 256; o <<= 1) {
        int x = (t >= o) ? sh[t - o] : 0;
        __syncthreads();
        sh[t] += x;
        __syncthreads();
    }
    int total = sh[255];
    if (t == 0) {
        if (b == 0) G_STATE[0] = (2ull << 32) | (unsigned)total;
        else        G_STATE[b] = (1ull << 32) | (unsigned)total;
    }
    if (t < 32) {
        int pfx = 0;
        if (b > 0) {
            int base_j = b - 1;
            for (;;) {
                int j = base_j - t;
                int flag, val;
                if (j >= 0) {
                    unsigned long long st;
                    do { st = G_STATE[j]; } while ((st >> 32) == 0);
                    flag = (int)(st >> 32); val = (int)(unsigned)st;
                } else { flag = 2; val = 0; }
                unsigned m2 = __ballot_sync(0xffffffffu, flag == 2);
                int first = __ffs(m2) - 1;
                int contrib = (m2 == 0) ? val : ((t <= first) ? val : 0);
#pragma unroll
                for (int o = 16; o; o >>= 1)
                    contrib += __shfl_xor_sync(0xffffffffu, contrib, o);
                pfx += contrib;
                if (m2) break;
                base_j -= 32;
            }
            if (t == 0) G_STATE[b] = (2ull << 32) | (unsigned)(pfx + total);
        }
        if (t == 0) s_prefix = pfx;
    }
    __syncthreads();
    int excl = s_prefix + sh[t] - s;
    int e0 = excl, e1 = excl + v0, e2 = e1 + v1, e3 = e2 + v2;
#pragma unroll
    for (int j = 0; j < 4; j++) {
        int n = base + j;
        if (n >= N_NODES) break;
        int r  = (j == 0) ? e0 : (j == 1) ? e1 : (j == 2) ? e2 : e3;
        int id = (j == 0) ? v0 : (j == 1) ? v1 : (j == 2) ? v2 : v3;
        g_dinfo[n].y = r;
        g_ninfo[n] = make_int2(r, id);
        int od = G_OUTDEG[n]; if (od < 1) od = 1;
        int idc = id < 1 ? 1 : id;
        g_outnorm[n] = rsqrtf((float)od);
        g_innorm[n]  = sqrtf((float)idc);
    }
}

// ---------------- K0: h = feat @ W^T via HMMA, grid-stride W-reuse --------
__global__ void __launch_bounds__(128) k_gemm(const float* __restrict__ feat,
                                              const float* __restrict__ W,
                                              const float* __restrict__ attn_l,
                                              const float* __restrict__ attn_r) {
    __shared__ __half sA[GEMM_TILE * APAD];
    __shared__ __half sB[OUT_F * APAD];
    int t = threadIdx.x;
    int warp = t >> 5, lane = t & 31;

    // W (64x128 fp32) -> sB fp16, once per block
#pragma unroll
    for (int i = 0; i < 16; i++) {
        int lin = t * 4 + i * 512;
        int o = lin >> 7, k = lin & 127;
        float4 w4 = __ldg((const float4*)(W + lin));
        *(__half2*)(sB + o * APAD + k)     = __floats2half2_rn(w4.x, w4.y);
        *(__half2*)(sB + o * APAD + k + 2) = __floats2half2_rn(w4.z, w4.w);
    }

    int m0 = warp * 16;
    int lr  = lane & 7;
    int grp = lane >> 3;
    int a_m = m0 + lr + ((grp & 1) ? 8 : 0);
    int a_k = (grp & 2) ? 8 : 0;
    unsigned aBase = smemu(sA) + (unsigned)(a_m * APAD + a_k) * 2;
    int b_n = lane & 7;
    int b_k = ((lane >> 3) & 1) ? 8 : 0;
    unsigned bBase = smemu(sB) + (unsigned)(b_n * APAD + b_k) * 2;

    int q  = lane & 3;
    int mr = lane >> 2;
    float2 alv[8], arv[8];
#pragma unroll
    for (int nt = 0; nt < 8; nt++) {
        alv[nt] = __ldg((const float2*)attn_l + nt * 4 + q);
        arv[nt] = __ldg((const float2*)attn_r + nt * 4 + q);
    }

    for (int tile = blockIdx.x; tile < GEMM_TILES; tile += gridDim.x) {
        int node0 = tile * GEMM_TILE;
        __syncthreads();   // sA free (prev ldmatrix done); also covers sB first time
#pragma unroll
        for (int i = 0; i < 16; i++) {
            int lin = t * 4 + i * 512;
            int r = lin >> 7, k = lin & 127;
            int node = node0 + r; if (node > N_NODES - 1) node = N_NODES - 1;
            float4 f4 = __ldg((const float4*)(feat + (size_t)node * IN_F + k));
            *(__half2*)(sA + r * APAD + k)     = __floats2half2_rn(f4.x, f4.y);
            *(__half2*)(sA + r * APAD + k + 2) = __floats2half2_rn(f4.z, f4.w);
        }
        __syncthreads();

        float c[8][4];
#pragma unroll
        for (int nt = 0; nt < 8; nt++) { c[nt][0] = c[nt][1] = c[nt][2] = c[nt][3] = 0.f; }

#pragma unroll
        for (int ks = 0; ks < 8; ks++) {
            unsigned a0, a1, a2, a3;
            asm volatile("ldmatrix.sync.aligned.m8n8.x4.shared.b16 {%0,%1,%2,%3}, [%4];"
                         : "=r"(a0), "=r"(a1), "=r"(a2), "=r"(a3)
                         : "r"(aBase + ks * 32));
#pragma unroll
            for (int nt = 0; nt < 8; nt++) {
                unsigned b0, b1;
                asm volatile("ldmatrix.sync.aligned.m8n8.x2.shared.b16 {%0,%1}, [%2];"
                             : "=r"(b0), "=r"(b1)
                             : "r"(bBase + nt * (8 * APAD * 2) + ks * 32));
                asm volatile("mma.sync.aligned.m16n8k16.row.col.f32.f16.f16.f32 "
                             "{%0,%1,%2,%3}, {%4,%5,%6,%7}, {%8,%9}, {%0,%1,%2,%3};"
                             : "+f"(c[nt][0]), "+f"(c[nt][1]), "+f"(c[nt][2]), "+f"(c[nt][3])
                             : "r"(a0), "r"(a1), "r"(a2), "r"(a3), "r"(b0), "r"(b1));
            }
        }

        int nodeA = node0 + m0 + mr;
        int nodeB = nodeA + 8;
        bool va = nodeA < N_NODES, vb = nodeB < N_NODES;
        float onA = va ? g_outnorm[nodeA] : 0.f;
        float onB = vb ? g_outnorm[nodeB] : 0.f;
        float el0 = 0.f, er0 = 0.f, el1 = 0.f, er1 = 0.f;
        __half2* h2 = (__half2*)g_h;
#pragma unroll
        for (int nt = 0; nt < 8; nt++) {
            el0 += c[nt][0] * alv[nt].x + c[nt][1] * alv[nt].y;
            er0 += c[nt][0] * arv[nt].x + c[nt][1] * arv[nt].y;
            el1 += c[nt][2] * alv[nt].x + c[nt][3] * alv[nt].y;
            er1 += c[nt][2] * arv[nt].x + c[nt][3] * arv[nt].y;
            if (va) h2[(size_t)nodeA * 32 + nt * 4 + q] =
                __floats2half2_rn(c[nt][0] * onA, c[nt][1] * onA);
            if (vb) h2[(size_t)nodeB * 32 + nt * 4 + q] =
                __floats2half2_rn(c[nt][2] * onB, c[nt][3] * onB);
        }
#pragma unroll
        for (int o = 1; o <= 2; o <<= 1) {
            el0 += __shfl_xor_sync(0xffffffffu, el0, o);
            er0 += __shfl_xor_sync(0xffffffffu, er0, o);
            el1 += __shfl_xor_sync(0xffffffffu, el1, o);
            er1 += __shfl_xor_sync(0xffffffffu, er1, o);
        }
        if (q == 0) {
            if (va) { g_el[nodeA] = el0; g_dinfo[nodeA].x = __float_as_int(er0); }
            if (vb) { g_el[nodeB] = el1; g_dinfo[nodeB].x = __float_as_int(er1); }
        }
    }
}

// ---------------- K3: edge pass, 2 edges/thread (no atomics) --------------
__global__ void k_edge2(const int2* __restrict__ src2, const int2* __restrict__ dst2) {
    int i = blockIdx.x * blockDim.x + threadIdx.x;
    if (i >= N_EDGES / 2) return;
    int2 s = __ldg(src2 + i);
    int2 d = __ldg(dst2 + i);
    unsigned rr = __ldg((const unsigned*)g_rank + i);   // ranks 2i, 2i+1
    int2 dia = __ldg(&g_dinfo[d.x]);
    int2 dib = __ldg(&g_dinfo[d.y]);
    float ea = __ldg(&g_el[s.x]) + __int_as_float(dia.x);
    float eb = __ldg(&g_el[s.y]) + __int_as_float(dib.x);
    ea = ea > 0.f ? ea : NEG_SLOPE * ea;
    eb = eb > 0.f ? eb : NEG_SLOPE * eb;
    float eea = __expf(ea), eeb = __expf(eb);
    g_pack[dia.y + (int)(rr & 0xffffu)] = make_int2(s.x, __float_as_int(eea));
    g_pack[dib.y + (int)(rr >> 16)]     = make_int2(s.y, __float_as_int(eeb));
}

// ---------------- K4: hop — 8 lanes/node, uint4 fp16 gathers --------------
__device__ __forceinline__ void fma8(float4& a0, float4& a1, float c, uint4 u) {
    float2 f;
    f = __half22float2(*(__half2*)&u.x); a0.x += c * f.x; a0.y += c * f.y;
    f = __half22float2(*(__half2*)&u.y); a0.z += c * f.x; a0.w += c * f.y;
    f = __half22float2(*(__half2*)&u.z); a1.x += c * f.x; a1.y += c * f.y;
    f = __half22float2(*(__half2*)&u.w); a1.z += c * f.x; a1.w += c * f.y;
}

// MODE 0: first hop  — denom = local sum of coefs; compute+cache scales
// MODE 1: middle hop — scale by cached scmid, write fp16 payload
// MODE 2: final hop  — scale by cached scfin, write fp32 output
template <int MODE>
__global__ void __launch_bounds__(256) k_hop(const __half* __restrict__ cur,
                                             void* __restrict__ nxt) {
    unsigned g = blockIdx.x * blockDim.x + threadIdx.x;
    unsigned n = g >> 3;
    if (n >= N_NODES) return;
    int lane = g & 7;
    int2 ni = __ldg(&g_ninfo[n]);            // {rowptr, indeg}
    int beg = ni.x;
    int end = beg + ni.y;
    const uint4* cur4 = (const uint4*)cur;   // 8 uint4 per row
    float4 a0 = make_float4(0.f, 0.f, 0.f, 0.f);
    float4 a1 = make_float4(0.f, 0.f, 0.f, 0.f);
    float dsum = 0.f;
    int p = beg;
    for (; p + 3 < end; p += 4) {
        int2 k0 = __ldg(&g_pack[p]);
        int2 k1 = __ldg(&g_pack[p + 1]);
        int2 k2 = __ldg(&g_pack[p + 2]);
        int2 k3 = __ldg(&g_pack[p + 3]);
        uint4 u0 = __ldg(&cur4[(size_t)k0.x * 8 + lane]);
        uint4 u1 = __ldg(&cur4[(size_t)k1.x * 8 + lane]);
        uint4 u2 = __ldg(&cur4[(size_t)k2.x * 8 + lane]);
        uint4 u3 = __ldg(&cur4[(size_t)k3.x * 8 + lane]);
        float c0 = __int_as_float(k0.y), c1 = __int_as_float(k1.y);
        float c2 = __int_as_float(k2.y), c3 = __int_as_float(k3.y);
        if (MODE == 0) dsum += (c0 + c1) + (c2 + c3);
        fma8(a0, a1, c0, u0); fma8(a0, a1, c1, u1);
        fma8(a0, a1, c2, u2); fma8(a0, a1, c3, u3);
    }
    for (; p < end; p++) {
        int2 k0 = __ldg(&g_pack[p]);
        uint4 u0 = __ldg(&cur4[(size_t)k0.x * 8 + lane]);
        float c0 = __int_as_float(k0.y);
        if (MODE == 0) dsum += c0;
        fma8(a0, a1, c0, u0);
    }
    float sc;
    if (MODE == 0) {
        float scfin = dsum > 0.f ? g_innorm[n] / dsum : 0.f;
        float scmid = scfin * g_outnorm[n];
        if (lane == 0) { g_innorm[n] = scmid; g_scfin[n] = scfin; }
        sc = scmid;
    } else if (MODE == 1) {
        sc = g_innorm[n];
    } else {
        sc = g_scfin[n];
    }
    a0.x *= sc; a0.y *= sc; a0.z *= sc; a0.w *= sc;
    a1.x *= sc; a1.y *= sc; a1.z *= sc; a1.w *= sc;
    if (MODE == 2) {
        ((float4*)nxt)[(size_t)n * 16 + lane * 2]     = a0;
        ((float4*)nxt)[(size_t)n * 16 + lane * 2 + 1] = a1;
    } else {
        __half2 h0 = __floats2half2_rn(a0.x, a0.y);
        __half2 h1 = __floats2half2_rn(a0.z, a0.w);
        __half2 h2 = __floats2half2_rn(a1.x, a1.y);
        __half2 h3 = __floats2half2_rn(a1.z, a1.w);
        uint4 u;
        u.x = *(unsigned*)&h0; u.y = *(unsigned*)&h1;
        u.z = *(unsigned*)&h2; u.w = *(unsigned*)&h3;
        ((uint4*)nxt)[(size_t)n * 8 + lane] = u;
    }
}

// ---------------- launch ----------------
extern "C" void kernel_launch(void* const* d_in, const int* in_sizes, int n_in,
                              void* d_out, int out_size) {
    const float* feat   = (const float*)d_in[0];
    const float* W      = (const float*)d_in[1];
    const float* attn_l = (const float*)d_in[2];
    const float* attn_r = (const float*)d_in[3];
    const int*   src    = (const int*)d_in[4];
    const int*   dst    = (const int*)d_in[5];
    float*       out    = (float*)d_out;

    void *p_zbuf, *p_x, *p_y, *p_h;
    cudaGetSymbolAddress(&p_zbuf, g_zbuf);
    cudaGetSymbolAddress(&p_x,    g_x);
    cudaGetSymbolAddress(&p_y,    g_y);
    cudaGetSymbolAddress(&p_h,    g_h);

    cudaMemsetAsync(p_zbuf, 0, ZBUF_BYTES);

    k_deg<<<(N_EDGES / 4 + 255) / 256, 256>>>((const int4*)src, (const int4*)dst);
    k_scan<<<SCAN_BLOCKS, 256>>>();
    k_gemm<<<GEMM_GRID, 128>>>(feat, W, attn_l, attn_r);
    k_edge2<<<(N_EDGES / 2 + 255) / 256, 256>>>((const int2*)src, (const int2*)dst);

    const int hop_blocks = (N_NODES * 8 + 255) / 256;  // 3125
    k_hop<0><<<hop_blocks, 256>>>((const __half*)p_h, p_x);
    k_hop<1><<<hop_blocks, 256>>>((const __half*)p_x, p_y);
    k_hop<2><<<hop_blocks, 256>>>((const __half*)p_y, out);
}

// round 16
// speedup vs baseline: 1.1250x; 1.0273x over previous
#include <cuda_runtime.h>
#include <cuda_fp16.h>

#define N_NODES 100000
#define N_EDGES 1600000
#define IN_F    128
#define OUT_F   64
#define NEG_SLOPE 0.2f
#define SCAN_ITEMS 1024
#define SCAN_BLOCKS ((N_NODES + SCAN_ITEMS - 1) / SCAN_ITEMS)   // 98
#define GEMM_TILE 64
#define GEMM_TILES ((N_NODES + GEMM_TILE - 1) / GEMM_TILE)      // 1563
#define GEMM_GRID 592
#define APAD 136   // padded half-row stride (conflict-free ldmatrix)

// ---------------- device scratch (static, allocation-free) ----------------
__device__ __half   g_h[N_NODES * OUT_F];     // fp16 payload: h * outnorm
__device__ __half   g_x[N_NODES * OUT_F];
__device__ __half   g_y[N_NODES * OUT_F];
__device__ float    g_el[N_NODES];
__device__ int2     g_dinfo[N_NODES];         // {er_bits, rowptr} for edge2
__device__ int2     g_ninfo[N_NODES];         // {rowptr, indeg} for hops
__device__ float    g_scfin[N_NODES];         // hop1 cache: innorm/denom
__device__ float    g_outnorm[N_NODES];
__device__ float    g_innorm[N_NODES];        // after hop1: scmid
__device__ unsigned short g_rank[N_EDGES];    // edge's within-dst-row rank
__device__ int2     g_pack[N_EDGES];          // {src, ee_bits}

// single zero-init region: [outdeg | indeg | lookback state]
__device__ int      g_zbuf[2 * N_NODES + 2 * SCAN_BLOCKS];
#define G_OUTDEG (g_zbuf)
#define G_INDEG  (g_zbuf + N_NODES)
#define G_STATE  ((volatile unsigned long long*)(g_zbuf + 2 * N_NODES))
#define ZBUF_BYTES ((2 * N_NODES + 2 * SCAN_BLOCKS) * sizeof(int))

__device__ __forceinline__ unsigned smemu(const void* p) {
    return (unsigned)__cvta_generic_to_shared(p);
}

// ---------------- K1: degrees + per-edge rank (4 edges/thread) ------------
__global__ void k_deg(const int4* __restrict__ src4, const int4* __restrict__ dst4) {
    int i = blockIdx.x * blockDim.x + threadIdx.x;
    if (i >= N_EDGES / 4) return;
    int4 s = __ldg(src4 + i);
    int4 d = __ldg(dst4 + i);
    atomicAdd(&G_OUTDEG[s.x], 1);
    atomicAdd(&G_OUTDEG[s.y], 1);
    atomicAdd(&G_OUTDEG[s.z], 1);
    atomicAdd(&G_OUTDEG[s.w], 1);
    ushort4 r;
    r.x = (unsigned short)atomicAdd(&G_INDEG[d.x], 1);
    r.y = (unsigned short)atomicAdd(&G_INDEG[d.y], 1);
    r.z = (unsigned short)atomicAdd(&G_INDEG[d.z], 1);
    r.w = (unsigned short)atomicAdd(&G_INDEG[d.w], 1);
    *(ushort4*)(g_rank + i * 4) = r;
}

// ---------------- K2: single-pass scan, warp-parallel lookback + norms ----
__global__ void __launch_bounds__(256) k_scan() {
    __shared__ int sh[256];
    __shared__ int s_prefix;
    int t = threadIdx.x, b = blockIdx.x;
    int base = b * SCAN_ITEMS + t * 4;
    int v0 = 0, v1 = 0, v2 = 0, v3 = 0;
    if (base + 0 < N_NODES) v0 = G_INDEG[base + 0];
    if (base + 1 < N_NODES) v1 = G_INDEG[base + 1];
    if (base + 2 < N_NODES) v2 = G_INDEG[base + 2];
    if (base + 3 < N_NODES) v3 = G_INDEG[base + 3];
    int s = v0 + v1 + v2 + v3;
    sh[t] = s;
    __syncthreads();
    for (int o = 1; o < 256; o <<= 1) {
        int x = (t >= o) ? sh[t - o] : 0;
        __syncthreads();
        sh[t] += x;
        __syncthreads();
    }
    int total = sh[255];
    if (t == 0) {
        if (b == 0) G_STATE[0] = (2ull << 32) | (unsigned)total;
        else        G_STATE[b] = (1ull << 32) | (unsigned)total;
    }
    if (t < 32) {
        int pfx = 0;
        if (b > 0) {
            int base_j = b - 1;
            for (;;) {
                int j = base_j - t;
                int flag, val;
                if (j >= 0) {
                    unsigned long long st;
                    do { st = G_STATE[j]; } while ((st >> 32) == 0);
                    flag = (int)(st >> 32); val = (int)(unsigned)st;
                } else { flag = 2; val = 0; }
                unsigned m2 = __ballot_sync(0xffffffffu, flag == 2);
                int first = __ffs(m2) - 1;
                int contrib = (m2 == 0) ? val : ((t <= first) ? val : 0);
#pragma unroll
                for (int o = 16; o; o >>= 1)
                    contrib += __shfl_xor_sync(0xffffffffu, contrib, o);
                pfx += contrib;
                if (m2) break;
                base_j -= 32;
            }
            if (t == 0) G_STATE[b] = (2ull << 32) | (unsigned)(pfx + total);
        }
        if (t == 0) s_prefix = pfx;
    }
    __syncthreads();
    int excl = s_prefix + sh[t] - s;
    int e0 = excl, e1 = excl + v0, e2 = e1 + v1, e3 = e2 + v2;
#pragma unroll
    for (int j = 0; j < 4; j++) {
        int n = base + j;
        if (n >= N_NODES) break;
        int r  = (j == 0) ? e0 : (j == 1) ? e1 : (j == 2) ? e2 : e3;
        int id = (j == 0) ? v0 : (j == 1) ? v1 : (j == 2) ? v2 : v3;
        g_dinfo[n].y = r;
        g_ninfo[n] = make_int2(r, id);
        int od = G_OUTDEG[n]; if (od < 1) od = 1;
        int idc = id < 1 ? 1 : id;
        g_outnorm[n] = rsqrtf((float)od);
        g_innorm[n]  = sqrtf((float)idc);
    }
}

// ---------------- K0: h = feat @ W^T via HMMA, grid-stride W-reuse --------
__global__ void __launch_bounds__(128) k_gemm(const float* __restrict__ feat,
                                              const float* __restrict__ W,
                                              const float* __restrict__ attn_l,
                                              const float* __restrict__ attn_r) {
    __shared__ __half sA[GEMM_TILE * APAD];
    __shared__ __half sB[OUT_F * APAD];
    int t = threadIdx.x;
    int warp = t >> 5, lane = t & 31;

#pragma unroll
    for (int i = 0; i < 16; i++) {
        int lin = t * 4 + i * 512;
        int o = lin >> 7, k = lin & 127;
        float4 w4 = __ldg((const float4*)(W + lin));
        *(__half2*)(sB + o * APAD + k)     = __floats2half2_rn(w4.x, w4.y);
        *(__half2*)(sB + o * APAD + k + 2) = __floats2half2_rn(w4.z, w4.w);
    }

    int m0 = warp * 16;
    int lr  = lane & 7;
    int grp = lane >> 3;
    int a_m = m0 + lr + ((grp & 1) ? 8 : 0);
    int a_k = (grp & 2) ? 8 : 0;
    unsigned aBase = smemu(sA) + (unsigned)(a_m * APAD + a_k) * 2;
    int b_n = lane & 7;
    int b_k = ((lane >> 3) & 1) ? 8 : 0;
    unsigned bBase = smemu(sB) + (unsigned)(b_n * APAD + b_k) * 2;

    int q  = lane & 3;
    int mr = lane >> 2;
    float2 alv[8], arv[8];
#pragma unroll
    for (int nt = 0; nt < 8; nt++) {
        alv[nt] = __ldg((const float2*)attn_l + nt * 4 + q);
        arv[nt] = __ldg((const float2*)attn_r + nt * 4 + q);
    }

    for (int tile = blockIdx.x; tile < GEMM_TILES; tile += gridDim.x) {
        int node0 = tile * GEMM_TILE;
        __syncthreads();
#pragma unroll
        for (int i = 0; i < 16; i++) {
            int lin = t * 4 + i * 512;
            int r = lin >> 7, k = lin & 127;
            int node = node0 + r; if (node > N_NODES - 1) node = N_NODES - 1;
            float4 f4 = __ldg((const float4*)(feat + (size_t)node * IN_F + k));
            *(__half2*)(sA + r * APAD + k)     = __floats2half2_rn(f4.x, f4.y);
            *(__half2*)(sA + r * APAD + k + 2) = __floats2half2_rn(f4.z, f4.w);
        }
        __syncthreads();

        float c[8][4];
#pragma unroll
        for (int nt = 0; nt < 8; nt++) { c[nt][0] = c[nt][1] = c[nt][2] = c[nt][3] = 0.f; }

#pragma unroll
        for (int ks = 0; ks < 8; ks++) {
            unsigned a0, a1, a2, a3;
            asm volatile("ldmatrix.sync.aligned.m8n8.x4.shared.b16 {%0,%1,%2,%3}, [%4];"
                         : "=r"(a0), "=r"(a1), "=r"(a2), "=r"(a3)
                         : "r"(aBase + ks * 32));
#pragma unroll
            for (int nt = 0; nt < 8; nt++) {
                unsigned b0, b1;
                asm volatile("ldmatrix.sync.aligned.m8n8.x2.shared.b16 {%0,%1}, [%2];"
                             : "=r"(b0), "=r"(b1)
                             : "r"(bBase + nt * (8 * APAD * 2) + ks * 32));
                asm volatile("mma.sync.aligned.m16n8k16.row.col.f32.f16.f16.f32 "
                             "{%0,%1,%2,%3}, {%4,%5,%6,%7}, {%8,%9}, {%0,%1,%2,%3};"
                             : "+f"(c[nt][0]), "+f"(c[nt][1]), "+f"(c[nt][2]), "+f"(c[nt][3])
                             : "r"(a0), "r"(a1), "r"(a2), "r"(a3), "r"(b0), "r"(b1));
            }
        }

        int nodeA = node0 + m0 + mr;
        int nodeB = nodeA + 8;
        bool va = nodeA < N_NODES, vb = nodeB < N_NODES;
        float onA = va ? g_outnorm[nodeA] : 0.f;
        float onB = vb ? g_outnorm[nodeB] : 0.f;
        float el0 = 0.f, er0 = 0.f, el1 = 0.f, er1 = 0.f;
        __half2* h2 = (__half2*)g_h;
#pragma unroll
        for (int nt = 0; nt < 8; nt++) {
            el0 += c[nt][0] * alv[nt].x + c[nt][1] * alv[nt].y;
            er0 += c[nt][0] * arv[nt].x + c[nt][1] * arv[nt].y;
            el1 += c[nt][2] * alv[nt].x + c[nt][3] * alv[nt].y;
            er1 += c[nt][2] * arv[nt].x + c[nt][3] * arv[nt].y;
            if (va) h2[(size_t)nodeA * 32 + nt * 4 + q] =
                __floats2half2_rn(c[nt][0] * onA, c[nt][1] * onA);
            if (vb) h2[(size_t)nodeB * 32 + nt * 4 + q] =
                __floats2half2_rn(c[nt][2] * onB, c[nt][3] * onB);
        }
#pragma unroll
        for (int o = 1; o <= 2; o <<= 1) {
            el0 += __shfl_xor_sync(0xffffffffu, el0, o);
            er0 += __shfl_xor_sync(0xffffffffu, er0, o);
            el1 += __shfl_xor_sync(0xffffffffu, el1, o);
            er1 += __shfl_xor_sync(0xffffffffu, er1, o);
        }
        if (q == 0) {
            if (va) { g_el[nodeA] = el0; g_dinfo[nodeA].x = __float_as_int(er0); }
            if (vb) { g_el[nodeB] = el1; g_dinfo[nodeB].x = __float_as_int(er1); }
        }
    }
}

// ---------------- K3: edge pass, 4 edges/thread (no atomics) --------------
__global__ void k_edge2(const int4* __restrict__ src4, const int4* __restrict__ dst4) {
    int i = blockIdx.x * blockDim.x + threadIdx.x;
    if (i >= N_EDGES / 4) return;
    int4 s = __ldg(src4 + i);
    int4 d = __ldg(dst4 + i);
    ushort4 r = __ldg((const ushort4*)g_rank + i);
    int2 di0 = __ldg(&g_dinfo[d.x]);
    int2 di1 = __ldg(&g_dinfo[d.y]);
    int2 di2 = __ldg(&g_dinfo[d.z]);
    int2 di3 = __ldg(&g_dinfo[d.w]);
    float l0 = __ldg(&g_el[s.x]);
    float l1 = __ldg(&g_el[s.y]);
    float l2 = __ldg(&g_el[s.z]);
    float l3 = __ldg(&g_el[s.w]);
    float e0 = l0 + __int_as_float(di0.x);
    float e1 = l1 + __int_as_float(di1.x);
    float e2 = l2 + __int_as_float(di2.x);
    float e3 = l3 + __int_as_float(di3.x);
    e0 = e0 > 0.f ? e0 : NEG_SLOPE * e0;
    e1 = e1 > 0.f ? e1 : NEG_SLOPE * e1;
    e2 = e2 > 0.f ? e2 : NEG_SLOPE * e2;
    e3 = e3 > 0.f ? e3 : NEG_SLOPE * e3;
    g_pack[di0.y + (int)r.x] = make_int2(s.x, __float_as_int(__expf(e0)));
    g_pack[di1.y + (int)r.y] = make_int2(s.y, __float_as_int(__expf(e1)));
    g_pack[di2.y + (int)r.z] = make_int2(s.z, __float_as_int(__expf(e2)));
    g_pack[di3.y + (int)r.w] = make_int2(s.w, __float_as_int(__expf(e3)));
}

// ---------------- K4: hop — 8 lanes/node, software-pipelined gathers ------
__device__ __forceinline__ void fma8(float4& a0, float4& a1, float c, uint4 u) {
    float2 f;
    f = __half22float2(*(__half2*)&u.x); a0.x += c * f.x; a0.y += c * f.y;
    f = __half22float2(*(__half2*)&u.y); a0.z += c * f.x; a0.w += c * f.y;
    f = __half22float2(*(__half2*)&u.z); a1.x += c * f.x; a1.y += c * f.y;
    f = __half22float2(*(__half2*)&u.w); a1.z += c * f.x; a1.w += c * f.y;
}

// MODE 0: first hop  — denom = local sum of coefs; compute+cache scales
// MODE 1: middle hop — scale by cached scmid, write fp16 payload
// MODE 2: final hop  — scale by cached scfin, write fp32 output
template <int MODE>
__global__ void __launch_bounds__(256) k_hop(const __half* __restrict__ cur,
                                             void* __restrict__ nxt) {
    unsigned g = blockIdx.x * blockDim.x + threadIdx.x;
    unsigned n = g >> 3;
    if (n >= N_NODES) return;
    int lane = g & 7;
    int2 ni = __ldg(&g_ninfo[n]);            // {rowptr, indeg}
    int beg = ni.x, deg = ni.y;
    const uint4* cur4 = (const uint4*)cur;   // 8 uint4 per row
    float4 a0 = make_float4(0.f, 0.f, 0.f, 0.f);
    float4 a1 = make_float4(0.f, 0.f, 0.f, 0.f);
    float dsum = 0.f;
    int nfull = deg >> 2;
    int p = beg + (nfull << 2);              // tail start
    if (nfull > 0) {
        int2 c0 = __ldg(&g_pack[beg]);
        int2 c1 = __ldg(&g_pack[beg + 1]);
        int2 c2 = __ldg(&g_pack[beg + 2]);
        int2 c3 = __ldg(&g_pack[beg + 3]);
        int pn = beg + 4;
        for (int b = 1; b < nfull; b++, pn += 4) {
            // prefetch next batch's records (overlaps with this batch's gathers)
            int2 n0 = __ldg(&g_pack[pn]);
            int2 n1 = __ldg(&g_pack[pn + 1]);
            int2 n2 = __ldg(&g_pack[pn + 2]);
            int2 n3 = __ldg(&g_pack[pn + 3]);
            uint4 u0 = __ldg(&cur4[(size_t)c0.x * 8 + lane]);
            uint4 u1 = __ldg(&cur4[(size_t)c1.x * 8 + lane]);
            uint4 u2 = __ldg(&cur4[(size_t)c2.x * 8 + lane]);
            uint4 u3 = __ldg(&cur4[(size_t)c3.x * 8 + lane]);
            float f0 = __int_as_float(c0.y), f1 = __int_as_float(c1.y);
            float f2 = __int_as_float(c2.y), f3 = __int_as_float(c3.y);
            if (MODE == 0) dsum += (f0 + f1) + (f2 + f3);
            fma8(a0, a1, f0, u0); fma8(a0, a1, f1, u1);
            fma8(a0, a1, f2, u2); fma8(a0, a1, f3, u3);
            c0 = n0; c1 = n1; c2 = n2; c3 = n3;
        }
        uint4 u0 = __ldg(&cur4[(size_t)c0.x * 8 + lane]);
        uint4 u1 = __ldg(&cur4[(size_t)c1.x * 8 + lane]);
        uint4 u2 = __ldg(&cur4[(size_t)c2.x * 8 + lane]);
        uint4 u3 = __ldg(&cur4[(size_t)c3.x * 8 + lane]);
        float f0 = __int_as_float(c0.y), f1 = __int_as_float(c1.y);
        float f2 = __int_as_float(c2.y), f3 = __int_as_float(c3.y);
        if (MODE == 0) dsum += (f0 + f1) + (f2 + f3);
        fma8(a0, a1, f0, u0); fma8(a0, a1, f1, u1);
        fma8(a0, a1, f2, u2); fma8(a0, a1, f3, u3);
    }
    for (int e = beg + deg; p < e; p++) {
        int2 k0 = __ldg(&g_pack[p]);
        uint4 u0 = __ldg(&cur4[(size_t)k0.x * 8 + lane]);
        float f0 = __int_as_float(k0.y);
        if (MODE == 0) dsum += f0;
        fma8(a0, a1, f0, u0);
    }
    float sc;
    if (MODE == 0) {
        float scfin = dsum > 0.f ? g_innorm[n] / dsum : 0.f;
        float scmid = scfin * g_outnorm[n];
        if (lane == 0) { g_innorm[n] = scmid; g_scfin[n] = scfin; }
        sc = scmid;
    } else if (MODE == 1) {
        sc = g_innorm[n];
    } else {
        sc = g_scfin[n];
    }
    a0.x *= sc; a0.y *= sc; a0.z *= sc; a0.w *= sc;
    a1.x *= sc; a1.y *= sc; a1.z *= sc; a1.w *= sc;
    if (MODE == 2) {
        ((float4*)nxt)[(size_t)n * 16 + lane * 2]     = a0;
        ((float4*)nxt)[(size_t)n * 16 + lane * 2 + 1] = a1;
    } else {
        __half2 h0 = __floats2half2_rn(a0.x, a0.y);
        __half2 h1 = __floats2half2_rn(a0.z, a0.w);
        __half2 h2 = __floats2half2_rn(a1.x, a1.y);
        __half2 h3 = __floats2half2_rn(a1.z, a1.w);
        uint4 u;
        u.x = *(unsigned*)&h0; u.y = *(unsigned*)&h1;
        u.z = *(unsigned*)&h2; u.w = *(unsigned*)&h3;
        ((uint4*)nxt)[(size_t)n * 8 + lane] = u;
    }
}

// ---------------- launch ----------------
extern "C" void kernel_launch(void* const* d_in, const int* in_sizes, int n_in,
                              void* d_out, int out_size) {
    const float* feat   = (const float*)d_in[0];
    const float* W      = (const float*)d_in[1];
    const float* attn_l = (const float*)d_in[2];
    const float* attn_r = (const float*)d_in[3];
    const int*   src    = (const int*)d_in[4];
    const int*   dst    = (const int*)d_in[5];
    float*       out    = (float*)d_out;

    void *p_zbuf, *p_x, *p_y, *p_h;
    cudaGetSymbolAddress(&p_zbuf, g_zbuf);
    cudaGetSymbolAddress(&p_x,    g_x);
    cudaGetSymbolAddress(&p_y,    g_y);
    cudaGetSymbolAddress(&p_h,    g_h);

    cudaMemsetAsync(p_zbuf, 0, ZBUF_BYTES);

    k_deg<<<(N_EDGES / 4 + 255) / 256, 256>>>((const int4*)src, (const int4*)dst);
    k_scan<<<SCAN_BLOCKS, 256>>>();
    k_gemm<<<GEMM_GRID, 128>>>(feat, W, attn_l, attn_r);
    k_edge2<<<(N_EDGES / 4 + 255) / 256, 256>>>((const int4*)src, (const int4*)dst);

    const int hop_blocks = (N_NODES * 8 + 255) / 256;  // 3125
    k_hop<0><<<hop_blocks, 256>>>((const __half*)p_h, p_x);
    k_hop<1><<<hop_blocks, 256>>>((const __half*)p_x, p_y);
    k_hop<2><<<hop_blocks, 256>>>((const __half*)p_y, out);
}